// round 1
// baseline (speedup 1.0000x reference)
#include <cuda_runtime.h>
#include <math_constants.h>

#define B_  64
#define S_  4096
#define DX_ 512
#define Q_  128
#define DQ_ 512

// split geometry: 8 blocks/batch * 16 warps/block = 128 warp-partials per batch
#define NB_      8
#define WPB_     16
#define WSPLITS_ (NB_ * WPB_)        // 128
#define RPW_     (S_ / WSPLITS_)     // 32 rows per warp

// scratch (static __device__ — allocation-free per harness rules)
__device__ float g_first[B_ * DX_];
__device__ float g_pm[B_ * WSPLITS_];
__device__ float g_pl[B_ * WSPLITS_];
__device__ float g_pctx[(size_t)B_ * WSPLITS_ * DX_];   // 16 MB

// ---------------------------------------------------------------------------
// Kernel 1: first[b,:] = (sum_q p[q] * Qm[b,q,:]) @ W      (tiny, ~5us)
// ---------------------------------------------------------------------------
__global__ void __launch_bounds__(512) compute_first_kernel(
    const float* __restrict__ qm,   // [B, Q, DQ]
    const float* __restrict__ Wm,   // [DQ, DX]
    const float* __restrict__ p)    // [Q]
{
    __shared__ float s_p[Q_];
    __shared__ float s_nq[DQ_];
    const int b = blockIdx.x;
    const int t = threadIdx.x;

    if (t < Q_) s_p[t] = p[t];
    __syncthreads();

    const float* qb = qm + (size_t)b * Q_ * DQ_;
    float acc = 0.f;
    #pragma unroll 4
    for (int q = 0; q < Q_; q++)
        acc += qb[(size_t)q * DQ_ + t] * s_p[q];
    s_nq[t] = acc;
    __syncthreads();

    float f = 0.f;
    #pragma unroll 4
    for (int d = 0; d < DQ_; d++)
        f += s_nq[d] * Wm[(size_t)d * DX_ + t];
    g_first[b * DX_ + t] = f;
}

// ---------------------------------------------------------------------------
// Kernel 2: fused scores + online softmax + context partials.
// One warp = one independent online-softmax over RPW_ rows (no block sync in
// the mainloop). x is read exactly ONCE -> DRAM-bound at ~512MB.
// ---------------------------------------------------------------------------
__global__ void __launch_bounds__(512, 2) attn_partial_kernel(
    const float* __restrict__ x)    // [B, S, DX]
{
    const int b    = blockIdx.y;
    const int warp = threadIdx.x >> 5;
    const int lane = threadIdx.x & 31;
    const int widx = blockIdx.x * WPB_ + warp;           // 0..127

    const float4* xb = (const float4*)(x + ((size_t)b * S_ + (size_t)widx * RPW_) * DX_);
    const float4* fp = (const float4*)(g_first + b * DX_);
    const float4 f0 = fp[lane], f1 = fp[32 + lane], f2 = fp[64 + lane], f3 = fp[96 + lane];

    float m = -CUDART_INF_F;
    float l = 0.f;
    float4 a0 = make_float4(0.f, 0.f, 0.f, 0.f), a1 = a0, a2 = a0, a3 = a0;

    #pragma unroll 1
    for (int r = 0; r < RPW_; r++) {
        const float4* xr = xb + (size_t)r * (DX_ / 4);
        const float4 x0 = xr[lane], x1 = xr[32 + lane], x2 = xr[64 + lane], x3 = xr[96 + lane];

        float s = f0.x*x0.x + f0.y*x0.y + f0.z*x0.z + f0.w*x0.w
                + f1.x*x1.x + f1.y*x1.y + f1.z*x1.z + f1.w*x1.w
                + f2.x*x2.x + f2.y*x2.y + f2.z*x2.z + f2.w*x2.w
                + f3.x*x3.x + f3.y*x3.y + f3.z*x3.z + f3.w*x3.w;
        #pragma unroll
        for (int o = 16; o; o >>= 1)
            s += __shfl_xor_sync(0xffffffffu, s, o);     // all lanes hold score

        if (s <= m) {
            // common path: max unchanged, no rescale of accumulator
            const float e = __expf(s - m);
            l += e;
            a0.x += e*x0.x; a0.y += e*x0.y; a0.z += e*x0.z; a0.w += e*x0.w;
            a1.x += e*x1.x; a1.y += e*x1.y; a1.z += e*x1.z; a1.w += e*x1.w;
            a2.x += e*x2.x; a2.y += e*x2.y; a2.z += e*x2.z; a2.w += e*x2.w;
            a3.x += e*x3.x; a3.y += e*x3.y; a3.z += e*x3.z; a3.w += e*x3.w;
        } else {
            // new max: e_new = 1, rescale history by exp(m_old - s)
            const float c = __expf(m - s);               // exp(-inf)=0 on first row
            l = l * c + 1.f;
            m = s;
            a0.x = a0.x*c + x0.x; a0.y = a0.y*c + x0.y; a0.z = a0.z*c + x0.z; a0.w = a0.w*c + x0.w;
            a1.x = a1.x*c + x1.x; a1.y = a1.y*c + x1.y; a1.z = a1.z*c + x1.z; a1.w = a1.w*c + x1.w;
            a2.x = a2.x*c + x2.x; a2.y = a2.y*c + x2.y; a2.z = a2.z*c + x2.z; a2.w = a2.w*c + x2.w;
            a3.x = a3.x*c + x3.x; a3.y = a3.y*c + x3.y; a3.z = a3.z*c + x3.z; a3.w = a3.w*c + x3.w;
        }
    }

    const int pi = b * WSPLITS_ + widx;
    if (lane == 0) { g_pm[pi] = m; g_pl[pi] = l; }
    float4* cp = (float4*)(g_pctx + (size_t)pi * DX_);
    cp[lane] = a0; cp[32 + lane] = a1; cp[64 + lane] = a2; cp[96 + lane] = a3;
}

// ---------------------------------------------------------------------------
// Kernel 3: merge 128 warp-partials per batch (reads 16.8MB total, ~3us)
// ---------------------------------------------------------------------------
__global__ void __launch_bounds__(512) attn_merge_kernel(float* __restrict__ out)
{
    const int b = blockIdx.x;
    const int t = threadIdx.x;

    __shared__ float s_w[WSPLITS_];
    __shared__ float s_L;

    if (t < 32) {
        float mx = -CUDART_INF_F;
        for (int i = t; i < WSPLITS_; i += 32)
            mx = fmaxf(mx, g_pm[b * WSPLITS_ + i]);
        #pragma unroll
        for (int o = 16; o; o >>= 1)
            mx = fmaxf(mx, __shfl_xor_sync(0xffffffffu, mx, o));

        float Ls = 0.f;
        for (int i = t; i < WSPLITS_; i += 32) {
            const float w = __expf(g_pm[b * WSPLITS_ + i] - mx);
            s_w[i] = w;
            Ls += g_pl[b * WSPLITS_ + i] * w;
        }
        #pragma unroll
        for (int o = 16; o; o >>= 1)
            Ls += __shfl_xor_sync(0xffffffffu, Ls, o);
        if (t == 0) s_L = Ls;
    }
    __syncthreads();

    const float inv = 1.0f / s_L;
    float sum = 0.f;
    #pragma unroll 4
    for (int i = 0; i < WSPLITS_; i++)
        sum += g_pctx[((size_t)b * WSPLITS_ + i) * DX_ + t] * s_w[i];
    out[(size_t)b * DX_ + t] = sum * inv;
}

// ---------------------------------------------------------------------------
extern "C" void kernel_launch(void* const* d_in, const int* in_sizes, int n_in,
                              void* d_out, int out_size)
{
    // identify inputs by element count (robust to ordering)
    const float* x  = nullptr;  // 64*4096*512 = 134217728
    const float* qm = nullptr;  // 64*128*512  = 4194304
    const float* Wm = nullptr;  // 512*512     = 262144
    const float* p  = nullptr;  // 128
    for (int i = 0; i < n_in; i++) {
        switch (in_sizes[i]) {
            case B_ * S_ * DX_: x  = (const float*)d_in[i]; break;
            case B_ * Q_ * DQ_: qm = (const float*)d_in[i]; break;
            case DQ_ * DX_:     Wm = (const float*)d_in[i]; break;
            case Q_:            p  = (const float*)d_in[i]; break;
            default: break;
        }
    }
    float* out = (float*)d_out;

    compute_first_kernel<<<B_, 512>>>(qm, Wm, p);
    dim3 g2(NB_, B_);
    attn_partial_kernel<<<g2, 512>>>(x);
    attn_merge_kernel<<<B_, 512>>>(out);
}

// round 2
// speedup vs baseline: 1.8414x; 1.8414x over previous
#include <cuda_runtime.h>
#include <math_constants.h>

#define B_  64
#define S_  4096
#define DX_ 512
#define Q_  128
#define DQ_ 512

// split geometry: 8 blocks/batch, 16 warps/block; each CTA reduces its 16
// warp-partials internally -> 8 block-partials per batch.
#define NB_      8
#define WPB_     16
#define WSPLITS_ (NB_ * WPB_)        // 128 warp-splits
#define RPW_     (S_ / WSPLITS_)     // 32 rows per warp

// scratch (static __device__ — allocation-free per harness rules)
__device__ __align__(16) float g_first[B_ * DX_];
__device__ float g_pm[B_ * NB_];
__device__ float g_pl[B_ * NB_];
__device__ __align__(16) float g_pctx[(size_t)B_ * NB_ * DX_];   // 1 MB

// ---------------------------------------------------------------------------
// Kernel 1: first[b,:] = (sum_q p[q] * Qm[b,q,:]) @ W
// Latency-bound fix: unroll 16 on both reduction loops (MLP=16).
// ---------------------------------------------------------------------------
__global__ void __launch_bounds__(512) compute_first_kernel(
    const float* __restrict__ qm,   // [B, Q, DQ]
    const float* __restrict__ Wm,   // [DQ, DX]
    const float* __restrict__ p)    // [Q]
{
    __shared__ float s_p[Q_];
    __shared__ float s_nq[DQ_];
    const int b = blockIdx.x;
    const int t = threadIdx.x;

    if (t < Q_) s_p[t] = p[t];
    __syncthreads();

    const float* qb = qm + (size_t)b * Q_ * DQ_ + t;
    float acc = 0.f;
    #pragma unroll 16
    for (int q = 0; q < Q_; q++)
        acc += qb[(size_t)q * DQ_] * s_p[q];
    s_nq[t] = acc;
    __syncthreads();

    const float* wc = Wm + t;
    float f = 0.f;
    #pragma unroll 16
    for (int d = 0; d < DQ_; d++)
        f += s_nq[d] * wc[(size_t)d * DX_];
    g_first[b * DX_ + t] = f;
}

// ---------------------------------------------------------------------------
// Kernel 2: fused scores + online softmax + context partials + CTA reduce.
// One warp = one independent online-softmax over RPW_ rows; x read ONCE
// (streaming) -> DRAM-bound at 512MB. 16 warp-partials merged in smem.
// ---------------------------------------------------------------------------
__global__ void __launch_bounds__(512, 2) attn_partial_kernel(
    const float* __restrict__ x)    // [B, S, DX]
{
    const int b    = blockIdx.y;
    const int warp = threadIdx.x >> 5;
    const int lane = threadIdx.x & 31;
    const int t    = threadIdx.x;
    const int widx = blockIdx.x * WPB_ + warp;           // 0..127

    __shared__ __align__(16) float s_ctx[WPB_][DX_];     // 32 KB
    __shared__ float s_m[WPB_], s_l[WPB_];

    const float4* xb = (const float4*)(x + ((size_t)b * S_ + (size_t)widx * RPW_) * DX_);
    const float4* fp = (const float4*)(g_first + b * DX_);
    const float4 f0 = fp[lane], f1 = fp[32 + lane], f2 = fp[64 + lane], f3 = fp[96 + lane];

    float m = -CUDART_INF_F;
    float l = 0.f;
    float4 a0 = make_float4(0.f, 0.f, 0.f, 0.f), a1 = a0, a2 = a0, a3 = a0;

    #pragma unroll 1
    for (int r = 0; r < RPW_; r++) {
        const float4* xr = xb + (size_t)r * (DX_ / 4);
        const float4 x0 = __ldcs(xr + lane);
        const float4 x1 = __ldcs(xr + 32 + lane);
        const float4 x2 = __ldcs(xr + 64 + lane);
        const float4 x3 = __ldcs(xr + 96 + lane);

        float s = f0.x*x0.x + f0.y*x0.y + f0.z*x0.z + f0.w*x0.w
                + f1.x*x1.x + f1.y*x1.y + f1.z*x1.z + f1.w*x1.w
                + f2.x*x2.x + f2.y*x2.y + f2.z*x2.z + f2.w*x2.w
                + f3.x*x3.x + f3.y*x3.y + f3.z*x3.z + f3.w*x3.w;
        #pragma unroll
        for (int o = 16; o; o >>= 1)
            s += __shfl_xor_sync(0xffffffffu, s, o);     // all lanes hold score

        if (s <= m) {
            // common path: max unchanged, no rescale of accumulator
            const float e = __expf(s - m);
            l += e;
            a0.x += e*x0.x; a0.y += e*x0.y; a0.z += e*x0.z; a0.w += e*x0.w;
            a1.x += e*x1.x; a1.y += e*x1.y; a1.z += e*x1.z; a1.w += e*x1.w;
            a2.x += e*x2.x; a2.y += e*x2.y; a2.z += e*x2.z; a2.w += e*x2.w;
            a3.x += e*x3.x; a3.y += e*x3.y; a3.z += e*x3.z; a3.w += e*x3.w;
        } else {
            // new max: e_new = 1, rescale history by exp(m_old - s)
            const float c = __expf(m - s);               // exp(-inf)=0 on first row
            l = l * c + 1.f;
            m = s;
            a0.x = a0.x*c + x0.x; a0.y = a0.y*c + x0.y; a0.z = a0.z*c + x0.z; a0.w = a0.w*c + x0.w;
            a1.x = a1.x*c + x1.x; a1.y = a1.y*c + x1.y; a1.z = a1.z*c + x1.z; a1.w = a1.w*c + x1.w;
            a2.x = a2.x*c + x2.x; a2.y = a2.y*c + x2.y; a2.z = a2.z*c + x2.z; a2.w = a2.w*c + x2.w;
            a3.x = a3.x*c + x3.x; a3.y = a3.y*c + x3.y; a3.z = a3.z*c + x3.z; a3.w = a3.w*c + x3.w;
        }
    }

    // --- CTA-level reduce of the 16 warp-partials (smem) ---
    {
        float4* row = (float4*)s_ctx[warp];
        row[lane] = a0; row[32 + lane] = a1; row[64 + lane] = a2; row[96 + lane] = a3;
        if (lane == 0) { s_m[warp] = m; s_l[warp] = l; }
    }
    __syncthreads();

    float M = -CUDART_INF_F;
    #pragma unroll
    for (int i = 0; i < WPB_; i++)
        M = fmaxf(M, s_m[i]);

    float L = 0.f, sum = 0.f;
    #pragma unroll
    for (int i = 0; i < WPB_; i++) {
        const float w = __expf(s_m[i] - M);
        L   += s_l[i] * w;
        sum += s_ctx[i][t] * w;
    }

    const int pi = b * NB_ + blockIdx.x;
    g_pctx[(size_t)pi * DX_ + t] = sum;
    if (t == 0) { g_pm[pi] = M; g_pl[pi] = L; }
}

// ---------------------------------------------------------------------------
// Kernel 3: merge 8 block-partials per batch (tiny: reads ~1MB total)
// ---------------------------------------------------------------------------
__global__ void __launch_bounds__(512) attn_merge_kernel(float* __restrict__ out)
{
    const int b = blockIdx.x;
    const int t = threadIdx.x;

    float M = -CUDART_INF_F;
    #pragma unroll
    for (int i = 0; i < NB_; i++)
        M = fmaxf(M, g_pm[b * NB_ + i]);

    float L = 0.f, sum = 0.f;
    #pragma unroll
    for (int i = 0; i < NB_; i++) {
        const float w = __expf(g_pm[b * NB_ + i] - M);
        L   += g_pl[b * NB_ + i] * w;
        sum += g_pctx[((size_t)b * NB_ + i) * DX_ + t] * w;
    }
    out[(size_t)b * DX_ + t] = sum / L;
}

// ---------------------------------------------------------------------------
extern "C" void kernel_launch(void* const* d_in, const int* in_sizes, int n_in,
                              void* d_out, int out_size)
{
    // identify inputs by element count (robust to ordering)
    const float* x  = nullptr;  // 64*4096*512 = 134217728
    const float* qm = nullptr;  // 64*128*512  = 4194304
    const float* Wm = nullptr;  // 512*512     = 262144
    const float* p  = nullptr;  // 128
    for (int i = 0; i < n_in; i++) {
        switch (in_sizes[i]) {
            case B_ * S_ * DX_: x  = (const float*)d_in[i]; break;
            case B_ * Q_ * DQ_: qm = (const float*)d_in[i]; break;
            case DQ_ * DX_:     Wm = (const float*)d_in[i]; break;
            case Q_:            p  = (const float*)d_in[i]; break;
            default: break;
        }
    }
    float* out = (float*)d_out;

    compute_first_kernel<<<B_, 512>>>(qm, Wm, p);
    dim3 g2(NB_, B_);
    attn_partial_kernel<<<g2, 512>>>(x);
    attn_merge_kernel<<<B_, 512>>>(out);
}

// round 3
// speedup vs baseline: 1.8516x; 1.0055x over previous
#include <cuda_runtime.h>
#include <math_constants.h>

#define B_  64
#define S_  4096
#define DX_ 512
#define Q_  128
#define DQ_ 512

// split geometry: 8 blocks/batch, 16 warps/block; each CTA reduces its 16
// warp-partials internally -> 8 block-partials per batch.
#define NB_      8
#define WPB_     16
#define WSPLITS_ (NB_ * WPB_)        // 128 warp-splits
#define RPW_     (S_ / WSPLITS_)     // 32 rows per warp

// scratch (static __device__ — allocation-free per harness rules)
__device__ __align__(16) float g_newq[B_ * DQ_];
__device__ __align__(16) float g_first[B_ * DX_];
__device__ float g_pm[B_ * NB_];
__device__ float g_pl[B_ * NB_];
__device__ __align__(16) float g_pctx[(size_t)B_ * NB_ * DX_];   // 1 MB

// ---------------------------------------------------------------------------
// Kernel 1a: new_q[b,:] = sum_q p[q] * Qm[b,q,:]
// Row-wise: each warp reads 8 contiguous 2KB rows with LDG.128, smem reduce.
// ---------------------------------------------------------------------------
__global__ void __launch_bounds__(512) newq_kernel(
    const float* __restrict__ qm,   // [B, Q, DQ]
    const float* __restrict__ p)    // [Q]
{
    __shared__ float s_p[Q_];
    __shared__ __align__(16) float s_acc[WPB_][DQ_];     // 32 KB
    const int b = blockIdx.x;
    const int t = threadIdx.x;
    const int w = t >> 5, lane = t & 31;

    if (t < Q_) s_p[t] = p[t];
    __syncthreads();

    float4 a0 = make_float4(0.f,0.f,0.f,0.f), a1 = a0, a2 = a0, a3 = a0;
    const float4* base = (const float4*)(qm + (size_t)b * Q_ * DQ_);

    #pragma unroll
    for (int q = w; q < Q_; q += WPB_) {
        const float4* row = base + (size_t)q * (DQ_ / 4);
        const float pq = s_p[q];
        const float4 r0 = row[lane], r1 = row[32+lane], r2 = row[64+lane], r3 = row[96+lane];
        a0.x += pq*r0.x; a0.y += pq*r0.y; a0.z += pq*r0.z; a0.w += pq*r0.w;
        a1.x += pq*r1.x; a1.y += pq*r1.y; a1.z += pq*r1.z; a1.w += pq*r1.w;
        a2.x += pq*r2.x; a2.y += pq*r2.y; a2.z += pq*r2.z; a2.w += pq*r2.w;
        a3.x += pq*r3.x; a3.y += pq*r3.y; a3.z += pq*r3.z; a3.w += pq*r3.w;
    }

    float4* sa = (float4*)s_acc[w];
    sa[lane] = a0; sa[32+lane] = a1; sa[64+lane] = a2; sa[96+lane] = a3;
    __syncthreads();

    float nq = 0.f;
    #pragma unroll
    for (int i = 0; i < WPB_; i++)
        nq += s_acc[i][t];
    g_newq[b * DQ_ + t] = nq;
}

// ---------------------------------------------------------------------------
// Kernel 1b: first[b,:] = new_q[b,:] @ W
// Row-wise: each warp reads 32 contiguous W rows with LDG.128 (same order in
// every CTA -> L2 broadcast), scales by s_nq[d], smem reduce.
// ---------------------------------------------------------------------------
__global__ void __launch_bounds__(512) first_kernel(
    const float* __restrict__ Wm)   // [DQ, DX]
{
    __shared__ float s_nq[DQ_];
    __shared__ __align__(16) float s_acc[WPB_][DX_];     // 32 KB
    const int b = blockIdx.x;
    const int t = threadIdx.x;
    const int w = t >> 5, lane = t & 31;

    s_nq[t] = g_newq[b * DQ_ + t];
    __syncthreads();

    float4 a0 = make_float4(0.f,0.f,0.f,0.f), a1 = a0, a2 = a0, a3 = a0;
    const float4* Wb = (const float4*)Wm;

    #pragma unroll 8
    for (int d = w; d < DQ_; d += WPB_) {
        const float4* row = Wb + (size_t)d * (DX_ / 4);
        const float nd = s_nq[d];
        const float4 r0 = row[lane], r1 = row[32+lane], r2 = row[64+lane], r3 = row[96+lane];
        a0.x += nd*r0.x; a0.y += nd*r0.y; a0.z += nd*r0.z; a0.w += nd*r0.w;
        a1.x += nd*r1.x; a1.y += nd*r1.y; a1.z += nd*r1.z; a1.w += nd*r1.w;
        a2.x += nd*r2.x; a2.y += nd*r2.y; a2.z += nd*r2.z; a2.w += nd*r2.w;
        a3.x += nd*r3.x; a3.y += nd*r3.y; a3.z += nd*r3.z; a3.w += nd*r3.w;
    }

    float4* sa = (float4*)s_acc[w];
    sa[lane] = a0; sa[32+lane] = a1; sa[64+lane] = a2; sa[96+lane] = a3;
    __syncthreads();

    float f = 0.f;
    #pragma unroll
    for (int i = 0; i < WPB_; i++)
        f += s_acc[i][t];
    g_first[b * DX_ + t] = f;
}

// ---------------------------------------------------------------------------
// Kernel 2: fused scores + online softmax + context partials + CTA reduce.
// One warp = one independent online-softmax over RPW_ rows; x read ONCE
// (streaming) -> DRAM-bound at 512MB. 16 warp-partials merged in smem.
// ---------------------------------------------------------------------------
__global__ void __launch_bounds__(512, 2) attn_partial_kernel(
    const float* __restrict__ x)    // [B, S, DX]
{
    const int b    = blockIdx.y;
    const int warp = threadIdx.x >> 5;
    const int lane = threadIdx.x & 31;
    const int t    = threadIdx.x;
    const int widx = blockIdx.x * WPB_ + warp;           // 0..127

    __shared__ __align__(16) float s_ctx[WPB_][DX_];     // 32 KB
    __shared__ float s_m[WPB_], s_l[WPB_];

    const float4* xb = (const float4*)(x + ((size_t)b * S_ + (size_t)widx * RPW_) * DX_);
    const float4* fp = (const float4*)(g_first + b * DX_);
    const float4 f0 = fp[lane], f1 = fp[32 + lane], f2 = fp[64 + lane], f3 = fp[96 + lane];

    float m = -CUDART_INF_F;
    float l = 0.f;
    float4 a0 = make_float4(0.f, 0.f, 0.f, 0.f), a1 = a0, a2 = a0, a3 = a0;

    #pragma unroll 1
    for (int r = 0; r < RPW_; r++) {
        const float4* xr = xb + (size_t)r * (DX_ / 4);
        const float4 x0 = __ldcs(xr + lane);
        const float4 x1 = __ldcs(xr + 32 + lane);
        const float4 x2 = __ldcs(xr + 64 + lane);
        const float4 x3 = __ldcs(xr + 96 + lane);

        float s = f0.x*x0.x + f0.y*x0.y + f0.z*x0.z + f0.w*x0.w
                + f1.x*x1.x + f1.y*x1.y + f1.z*x1.z + f1.w*x1.w
                + f2.x*x2.x + f2.y*x2.y + f2.z*x2.z + f2.w*x2.w
                + f3.x*x3.x + f3.y*x3.y + f3.z*x3.z + f3.w*x3.w;
        #pragma unroll
        for (int o = 16; o; o >>= 1)
            s += __shfl_xor_sync(0xffffffffu, s, o);     // all lanes hold score

        if (s <= m) {
            // common path: max unchanged, no rescale of accumulator
            const float e = __expf(s - m);
            l += e;
            a0.x += e*x0.x; a0.y += e*x0.y; a0.z += e*x0.z; a0.w += e*x0.w;
            a1.x += e*x1.x; a1.y += e*x1.y; a1.z += e*x1.z; a1.w += e*x1.w;
            a2.x += e*x2.x; a2.y += e*x2.y; a2.z += e*x2.z; a2.w += e*x2.w;
            a3.x += e*x3.x; a3.y += e*x3.y; a3.z += e*x3.z; a3.w += e*x3.w;
        } else {
            // new max: e_new = 1, rescale history by exp(m_old - s)
            const float c = __expf(m - s);               // exp(-inf)=0 on first row
            l = l * c + 1.f;
            m = s;
            a0.x = a0.x*c + x0.x; a0.y = a0.y*c + x0.y; a0.z = a0.z*c + x0.z; a0.w = a0.w*c + x0.w;
            a1.x = a1.x*c + x1.x; a1.y = a1.y*c + x1.y; a1.z = a1.z*c + x1.z; a1.w = a1.w*c + x1.w;
            a2.x = a2.x*c + x2.x; a2.y = a2.y*c + x2.y; a2.z = a2.z*c + x2.z; a2.w = a2.w*c + x2.w;
            a3.x = a3.x*c + x3.x; a3.y = a3.y*c + x3.y; a3.z = a3.z*c + x3.z; a3.w = a3.w*c + x3.w;
        }
    }

    // --- CTA-level reduce of the 16 warp-partials (smem) ---
    {
        float4* row = (float4*)s_ctx[warp];
        row[lane] = a0; row[32 + lane] = a1; row[64 + lane] = a2; row[96 + lane] = a3;
        if (lane == 0) { s_m[warp] = m; s_l[warp] = l; }
    }
    __syncthreads();

    float M = -CUDART_INF_F;
    #pragma unroll
    for (int i = 0; i < WPB_; i++)
        M = fmaxf(M, s_m[i]);

    float L = 0.f, sum = 0.f;
    #pragma unroll
    for (int i = 0; i < WPB_; i++) {
        const float w = __expf(s_m[i] - M);
        L   += s_l[i] * w;
        sum += s_ctx[i][t] * w;
    }

    const int pi = b * NB_ + blockIdx.x;
    g_pctx[(size_t)pi * DX_ + t] = sum;
    if (t == 0) { g_pm[pi] = M; g_pl[pi] = L; }
}

// ---------------------------------------------------------------------------
// Kernel 3: merge 8 block-partials per batch (tiny: reads ~1MB total)
// ---------------------------------------------------------------------------
__global__ void __launch_bounds__(512) attn_merge_kernel(float* __restrict__ out)
{
    const int b = blockIdx.x;
    const int t = threadIdx.x;

    float M = -CUDART_INF_F;
    #pragma unroll
    for (int i = 0; i < NB_; i++)
        M = fmaxf(M, g_pm[b * NB_ + i]);

    float L = 0.f, sum = 0.f;
    #pragma unroll
    for (int i = 0; i < NB_; i++) {
        const float w = __expf(g_pm[b * NB_ + i] - M);
        L   += g_pl[b * NB_ + i] * w;
        sum += g_pctx[((size_t)b * NB_ + i) * DX_ + t] * w;
    }
    out[(size_t)b * DX_ + t] = sum / L;
}

// ---------------------------------------------------------------------------
extern "C" void kernel_launch(void* const* d_in, const int* in_sizes, int n_in,
                              void* d_out, int out_size)
{
    // identify inputs by element count (robust to ordering)
    const float* x  = nullptr;  // 64*4096*512 = 134217728
    const float* qm = nullptr;  // 64*128*512  = 4194304
    const float* Wm = nullptr;  // 512*512     = 262144
    const float* p  = nullptr;  // 128
    for (int i = 0; i < n_in; i++) {
        switch (in_sizes[i]) {
            case B_ * S_ * DX_: x  = (const float*)d_in[i]; break;
            case B_ * Q_ * DQ_: qm = (const float*)d_in[i]; break;
            case DQ_ * DX_:     Wm = (const float*)d_in[i]; break;
            case Q_:            p  = (const float*)d_in[i]; break;
            default: break;
        }
    }
    float* out = (float*)d_out;

    newq_kernel<<<B_, 512>>>(qm, p);
    first_kernel<<<B_, 512>>>(Wm);
    dim3 g2(NB_, B_);
    attn_partial_kernel<<<g2, 512>>>(x);
    attn_merge_kernel<<<B_, 512>>>(out);
}